// round 7
// baseline (speedup 1.0000x reference)
#include <cuda_runtime.h>
#include <cstdint>

#define CIN      64
#define COUT     64
#define BATCH    16
#define IM       32
#define LOCS     1024      // 32*32 output locations
#define KVOL     576       // CIN * 3 * 3
#define PSTR     20        // patch smem row stride (floats): 16B-aligned, conflict-free
#define OSTRIDE  589824    // LOCS * KVOL

// ---------------- scratch ----------------
__device__ float g_y[LOCS * 1024];      // [loc][b*64+o]
__device__ float g_psum[LOCS * COUT];
__device__ float g_psumsq[LOCS * COUT];
__device__ float g_scale[COUT];
__device__ float g_shift[COUT];

// ---------------- f32x2 helpers ----------------
__device__ __forceinline__ unsigned long long pk2(float lo, float hi) {
    unsigned long long r;
    asm("mov.b64 %0, {%1, %2};" : "=l"(r)
        : "r"(__float_as_uint(lo)), "r"(__float_as_uint(hi)));
    return r;
}
__device__ __forceinline__ float2 upk(unsigned long long v) {
    unsigned u0, u1;
    asm("mov.b64 {%0, %1}, %2;" : "=r"(u0), "=r"(u1) : "l"(v));
    return make_float2(__uint_as_float(u0), __uint_as_float(u1));
}
__device__ __forceinline__ void fma2(unsigned long long& d, unsigned long long a,
                                     unsigned long long b) {
    asm("fma.rn.f32x2 %0, %1, %2, %0;" : "+l"(d) : "l"(a), "l"(b));
}

// Physical patch-row swizzle: lane owns 4 consecutive k (vector weight loads) but
// reads smem with lane-stride of ONE physical row (conflict-free with PSTR=20).
//   main blocks (k < 512):  k = blk*128 + 4L + j  ->  phys = blk*128 + (j<<5) + L
//   tail        (k >= 512): k = 512 + 2L + j      ->  phys = 512 + (j<<5) + L
__device__ __forceinline__ int sigma(int k) {
    if (k < 512) return (k & ~127) | ((k & 3) << 5) | ((k >> 2) & 31);
    return 512 + ((k & 1) << 5) + ((k >> 1) & 31);
}

// ---------------- kernel 1: locally-connected conv + bias + partial stats ----------------
__global__ __launch_bounds__(512, 1)
void conv_kernel(const float* __restrict__ x, const float* __restrict__ w,
                 const float* __restrict__ bias) {
    __shared__ __align__(16) float ps[KVOL * PSTR];   // 46080 B patches [phys_row][b]

    const int tid = threadIdx.x;
    const int loc = blockIdx.x;
    const int i0 = loc >> 5, j0 = loc & 31;

    const int lane = tid & 31;
    const int wid  = tid >> 5;
    const int ob   = wid * 4;                       // this warp's o-quad
    const float* wp = w + (size_t)ob * OSTRIDE + (size_t)loc * KVOL;

    // Prefetch weight block 0 BEFORE the gather barrier (addresses independent of smem):
    // DRAM latency of the first block hides entirely behind phase 1.
    float4 wc[4], wn[4];
    float2 wt[4];
#pragma unroll
    for (int oo = 0; oo < 4; oo++)
        wc[oo] = *(const float4*)(wp + (size_t)oo * OSTRIDE + lane * 4);

    // ---- Phase 1: cooperative gather ----
    // row r = (b*64+c)*3 + pp (3072 rows); 4 lanes per row read jj = j0-1+j; keep j<=2.
    // Per warp-instr: 8 row-windows -> ~8 L1 wavefronts (vs 32 for the b-fast layout).
    {
        const int j    = tid & 3;
        const int slot = tid >> 2;                 // 0..127
#pragma unroll 4
        for (int it = 0; it < 24; it++) {
            int r   = slot + (it << 7);
            int b   = r / 192;
            int rem = r - b * 192;
            int c   = rem / 3;
            int pp  = rem - c * 3;
            int ii  = i0 + pp - 1;
            int jj  = j0 - 1 + j;
            float v = 0.0f;
            if ((unsigned)ii < 32u && (unsigned)jj < 32u)
                v = x[((b * 64 + c) * 32 + ii) * 32 + jj];
            if (j <= 2)
                ps[sigma(c * 9 + pp * 3 + j) * PSTR + b] = v;
        }
    }
    __syncthreads();

    // ---- Mainloop ----
    unsigned long long acc[32];                     // acc[oo*8+bp] = (y[2bp], y[2bp+1]) for o=ob+oo
#pragma unroll
    for (int v = 0; v < 32; v++) acc[v] = 0ULL;

#pragma unroll
    for (int blk = 0; blk < 4; blk++) {
        if (blk < 3) {
#pragma unroll
            for (int oo = 0; oo < 4; oo++)
                wn[oo] = *(const float4*)(wp + (size_t)oo * OSTRIDE + (blk + 1) * 128 + lane * 4);
        } else {
#pragma unroll
            for (int oo = 0; oo < 4; oo++)
                wt[oo] = *(const float2*)(wp + (size_t)oo * OSTRIDE + 512 + lane * 2);
        }
#pragma unroll
        for (int j = 0; j < 4; j++) {
            const float* pr = &ps[(blk * 128 + (j << 5) + lane) * PSTR];
            unsigned long long pb[8];
#pragma unroll
            for (int h = 0; h < 4; h++) {
                ulonglong2 u = *(const ulonglong2*)(pr + h * 4);
                pb[h * 2] = u.x;
                pb[h * 2 + 1] = u.y;
            }
#pragma unroll
            for (int oo = 0; oo < 4; oo++) {
                float wv = (j == 0) ? wc[oo].x : (j == 1) ? wc[oo].y
                         : (j == 2) ? wc[oo].z : wc[oo].w;
                unsigned long long wd = pk2(wv, wv);
#pragma unroll
                for (int bp = 0; bp < 8; bp++)
                    fma2(acc[oo * 8 + bp], wd, pb[bp]);
            }
        }
        if (blk < 3) {
#pragma unroll
            for (int oo = 0; oo < 4; oo++) wc[oo] = wn[oo];
        }
    }
    // tail: k = 512 + lane*2 + j, j in {0,1}
#pragma unroll
    for (int j = 0; j < 2; j++) {
        const float* pr = &ps[(512 + (j << 5) + lane) * PSTR];
        unsigned long long pb[8];
#pragma unroll
        for (int h = 0; h < 4; h++) {
            ulonglong2 u = *(const ulonglong2*)(pr + h * 4);
            pb[h * 2] = u.x;
            pb[h * 2 + 1] = u.y;
        }
#pragma unroll
        for (int oo = 0; oo < 4; oo++) {
            float wv = j ? wt[oo].y : wt[oo].x;
            unsigned long long wd = pk2(wv, wv);
#pragma unroll
            for (int bp = 0; bp < 8; bp++)
                fma2(acc[oo * 8 + bp], wd, pb[bp]);
        }
    }

    // Split-butterfly cross-lane reduction: lane L ends with acc for (oo=L>>3, bp=L&7)
#pragma unroll
    for (int off = 16; off >= 1; off >>= 1) {
        const bool up = (lane & off) != 0;
#pragma unroll
        for (int v = 0; v < off; v++) {
            unsigned long long give = up ? acc[v] : acc[v + off];
            unsigned long long keep = up ? acc[v + off] : acc[v];
            float2 g = upk(give);
            g.x = __shfl_xor_sync(0xffffffffu, g.x, off);
            g.y = __shfl_xor_sync(0xffffffffu, g.y, off);
            float2 kf = upk(keep);
            acc[v] = pk2(kf.x + g.x, kf.y + g.y);
        }
    }

    const int oo = lane >> 3, bp = lane & 7;
    const int o = ob + oo;
    const float bz = bias[o * LOCS + loc];
    float2 yv = upk(acc[0]);
    const float y0 = yv.x + bz;
    const float y1 = yv.y + bz;

    // per-channel partial stats (deterministic shfl tree)
    float s  = y0 + y1;
    float q2 = y0 * y0 + y1 * y1;
#pragma unroll
    for (int off = 4; off >= 1; off >>= 1) {
        s  += __shfl_xor_sync(0xffffffffu, s, off);
        q2 += __shfl_xor_sync(0xffffffffu, q2, off);
    }
    if (bp == 0) {
        g_psum[loc * COUT + o]   = s;
        g_psumsq[loc * COUT + o] = q2;
    }

    // stage outputs in smem, one coalesced 4KB store
    __syncthreads();
    float* buf = ps;
    buf[(bp * 2) * COUT + o]     = y0;
    buf[(bp * 2 + 1) * COUT + o] = y1;
    __syncthreads();
    if (tid < 256) {
        float4* dst = (float4*)&g_y[loc * 1024];
        const float4* src = (const float4*)buf;
        dst[tid] = src[tid];
    }
}

// ---------------- kernel 2: finalize batch statistics ----------------
__global__ __launch_bounds__(256)
void stats_kernel(const float* __restrict__ gamma, const float* __restrict__ beta) {
    __shared__ float ss[256], sq[256];
    const int o = blockIdx.x, t = threadIdx.x;
    float s = 0.0f, q = 0.0f;
    for (int l = t; l < LOCS; l += 256) {
        s += g_psum[l * COUT + o];
        q += g_psumsq[l * COUT + o];
    }
    ss[t] = s; sq[t] = q;
    __syncthreads();
#pragma unroll
    for (int h = 128; h >= 1; h >>= 1) {
        if (t < h) { ss[t] += ss[t + h]; sq[t] += sq[t + h]; }
        __syncthreads();
    }
    if (t == 0) {
        const float N = (float)(BATCH * LOCS);
        float mean = ss[0] / N;
        float var  = sq[0] / N - mean * mean;
        float sc   = gamma[o] * rsqrtf(var + 1e-5f);
        g_scale[o] = sc;
        g_shift[o] = beta[o] - mean * sc;
    }
}

// ---------------- kernel 3: tiled transpose + BN affine + ReLU ----------------
__global__ __launch_bounds__(256)
void bn_kernel(float* __restrict__ out) {
    __shared__ float tile[32][33];
    __shared__ float s_sc[32], s_sh[32];
    const int t = threadIdx.x;
    const int tx = blockIdx.x;   // bo tile
    const int ty = blockIdx.y;   // loc tile
    if (t < 32) {
        int o = (tx * 32 + t) & 63;
        s_sc[t] = g_scale[o];
        s_sh[t] = g_shift[o];
    }
    const int lr = t >> 5;
    const int lc = t & 31;
#pragma unroll
    for (int p = 0; p < 4; p++) {
        int r = p * 8 + lr;
        tile[r][lc] = g_y[(ty * 32 + r) * 1024 + tx * 32 + lc];
    }
    __syncthreads();
#pragma unroll
    for (int p = 0; p < 4; p++) {
        int r = p * 8 + lr;
        int bo  = tx * 32 + r;
        int loc = ty * 32 + lc;
        float v = tile[lc][r] * s_sc[r] + s_sh[r];
        out[bo * 1024 + loc] = fmaxf(v, 0.0f);
    }
}

// ---------------- launch ----------------
extern "C" void kernel_launch(void* const* d_in, const int* in_sizes, int n_in,
                              void* d_out, int out_size) {
    const float* x     = (const float*)d_in[0];
    const float* w     = (const float*)d_in[1];
    const float* bias  = (const float*)d_in[2];
    const float* gamma = (const float*)d_in[3];
    const float* beta  = (const float*)d_in[4];
    float* out = (float*)d_out;

    conv_kernel<<<LOCS, 512>>>(x, w, bias);
    stats_kernel<<<COUT, 256>>>(gamma, beta);
    bn_kernel<<<dim3(32, 32), 256>>>(out);
}

// round 8
// speedup vs baseline: 1.3597x; 1.3597x over previous
#include <cuda_runtime.h>
#include <cstdint>

#define CIN      64
#define COUT     64
#define BATCH    16
#define IM       32
#define LOCS     1024      // 32*32 output locations
#define KVOL     576       // CIN * 3 * 3
#define KHALF    288       // per-half reduction length (32 input channels)
#define PSTR     20        // patch smem row stride (floats): 16B-aligned, conflict-free
#define OSTRIDE  589824    // LOCS * KVOL
#define CHUNKK   32        // k per weight chunk
#define NCHUNK   9         // chunks per half (288/32)
#define NSLOT    3         // ring slots

// ---------------- scratch ----------------
__device__ float g_y[LOCS * 1024];      // [loc][b*64+o]
__device__ float g_psum[LOCS * COUT];
__device__ float g_psumsq[LOCS * COUT];
__device__ float g_scale[COUT];
__device__ float g_shift[COUT];

// ---------------- f32x2 helpers ----------------
__device__ __forceinline__ unsigned long long pk2(float lo, float hi) {
    unsigned long long r;
    asm("mov.b64 %0, {%1, %2};" : "=l"(r)
        : "r"(__float_as_uint(lo)), "r"(__float_as_uint(hi)));
    return r;
}
__device__ __forceinline__ float2 upk(unsigned long long v) {
    unsigned u0, u1;
    asm("mov.b64 {%0, %1}, %2;" : "=r"(u0), "=r"(u1) : "l"(v));
    return make_float2(__uint_as_float(u0), __uint_as_float(u1));
}
__device__ __forceinline__ void fma2(unsigned long long& d, unsigned long long a,
                                     unsigned long long b) {
    asm("fma.rn.f32x2 %0, %1, %2, %0;" : "+l"(d) : "l"(a), "l"(b));
}

// ---------------- cp.async helpers ----------------
__device__ __forceinline__ void cp16(uint32_t dst_smem, const void* src) {
    asm volatile("cp.async.cg.shared.global [%0], [%1], 16;" ::
                 "r"(dst_smem), "l"(src) : "memory");
}
__device__ __forceinline__ void cp_commit() {
    asm volatile("cp.async.commit_group;" ::: "memory");
}
__device__ __forceinline__ void cp_wait1() {
    asm volatile("cp.async.wait_group 1;" ::: "memory");
}
__device__ __forceinline__ void cp_wait0() {
    asm volatile("cp.async.wait_group 0;" ::: "memory");
}

// ---------------- kernel 1: conv + bias + partial stats ----------------
// One CTA (512 thr, 16 warps) per location. K processed in 2 halves of 288.
// Weights stream through a 3-slot smem ring via cp.async (16KB in flight).
// Warp w owns o-quad [4w,4w+4); lane owns k = chunk*32 + lane.
__global__ __launch_bounds__(512, 1)
void conv_kernel(const float* __restrict__ x, const float* __restrict__ w,
                 const float* __restrict__ bias) {
    __shared__ __align__(16) float ps[KHALF * PSTR];        // 23040 B patches [k_local][b]
    __shared__ __align__(16) float wring[NSLOT][64 * CHUNKK]; // 3 x 8KB weight ring [o][k]

    const int tid = threadIdx.x;
    const int loc = blockIdx.x;
    const int i0 = loc >> 5, j0 = loc & 31;

    const int lane = tid & 31;
    const int wid  = tid >> 5;
    const int ob   = wid * 4;

    const float* wbase = w + (size_t)loc * KVOL;   // o=0 row for this location
    // per-thread cp.async source/dest offsets: o = tid>>3, 16B seg = tid&7
    const int cp_o   = tid >> 3;
    const int cp_seg = (tid & 7) * 4;              // float offset within 32-float row
    const uint32_t cp_dst_base =
        (uint32_t)__cvta_generic_to_shared(&wring[0][0]) + (cp_o * CHUNKK + cp_seg) * 4;
    const float* cp_src_base = wbase + (size_t)cp_o * OSTRIDE + cp_seg;

    unsigned long long acc[32];                    // acc[oo*8+bp]: (y[2bp],y[2bp+1]) for o=ob+oo
#pragma unroll
    for (int v = 0; v < 32; v++) acc[v] = 0ULL;

    // Prologue: issue half-0 chunks 0,1 (slots 0,1) before the gather
    cp16(cp_dst_base + 0 * 64 * CHUNKK * 4, cp_src_base + 0);       cp_commit();
    cp16(cp_dst_base + 1 * 64 * CHUNKK * 4, cp_src_base + CHUNKK); cp_commit();

    const int gj    = tid & 3;
    const int gslot = tid >> 2;                    // 0..127

#pragma unroll 1
    for (int h = 0; h < 2; h++) {
        // ---- gather patches for this half (32 input channels) ----
        __syncthreads();                           // prior-half readers done with ps
#pragma unroll
        for (int it = 0; it < 12; it++) {
            int r   = gslot + (it << 7);           // 0..1535 = b*96 + c*3 + pp
            int b   = (r * 683) >> 16;             // r / 96 (exact for r<1536)
            int rem = r - b * 96;
            int c   = (rem * 21846) >> 16;         // rem / 3 (exact for rem<96)
            int pp  = rem - c * 3;
            int ii  = i0 + pp - 1;
            int jj  = j0 - 1 + gj;
            float v = 0.0f;
            if (((unsigned)ii < 32u) & ((unsigned)jj < 32u))
                v = x[((b * 64 + h * 32 + c) * 32 + ii) * 32 + jj];
            if (gj <= 2)
                ps[(c * 9 + pp * 3 + gj) * PSTR + b] = v;
        }
        __syncthreads();

        // ---- chunk loop: 9 chunks of k=32 ----
#pragma unroll 1
        for (int cc = 0; cc < NCHUNK; cc++) {
            if (cc < NCHUNK - 1) cp_wait1(); else cp_wait0();
            __syncthreads();                       // chunk cc visible to all

            if (cc < NCHUNK - 2) {
                // issue chunk cc+2 into slot (cc+2)%3 (safe: last read at iter cc-1)
                int nc   = cc + 2;
                int slot = nc % NSLOT;
                cp16(cp_dst_base + slot * 64 * CHUNKK * 4,
                     cp_src_base + h * KHALF + nc * CHUNKK);
                cp_commit();
            } else if (cc == NCHUNK - 1 && h == 0) {
                // prefetch half-1 chunks 0,1 into slots 0,1 (free after iters 6,7)
                cp16(cp_dst_base + 0 * 64 * CHUNKK * 4, cp_src_base + KHALF + 0);
                cp_commit();
                cp16(cp_dst_base + 1 * 64 * CHUNKK * 4, cp_src_base + KHALF + CHUNKK);
                cp_commit();
            }

            // ---- compute chunk cc ----
            const float* Wc = &wring[cc % NSLOT][0];
            float wv[4];
#pragma unroll
            for (int oo = 0; oo < 4; oo++)
                wv[oo] = Wc[(ob + oo) * CHUNKK + lane];

            const float* pr = &ps[(cc * CHUNKK + lane) * PSTR];
            unsigned long long pb[8];
#pragma unroll
            for (int hh = 0; hh < 4; hh++) {
                ulonglong2 u = *(const ulonglong2*)(pr + hh * 4);
                pb[hh * 2]     = u.x;
                pb[hh * 2 + 1] = u.y;
            }
#pragma unroll
            for (int oo = 0; oo < 4; oo++) {
                unsigned long long wd = pk2(wv[oo], wv[oo]);
#pragma unroll
                for (int bp = 0; bp < 8; bp++)
                    fma2(acc[oo * 8 + bp], wd, pb[bp]);
            }
        }
    }

    // ---- butterfly reduction: lane L ends with acc for (oo=L>>3, bp=L&7) ----
#pragma unroll
    for (int off = 16; off >= 1; off >>= 1) {
        const bool up = (lane & off) != 0;
#pragma unroll
        for (int v = 0; v < off; v++) {
            unsigned long long give = up ? acc[v] : acc[v + off];
            unsigned long long keep = up ? acc[v + off] : acc[v];
            float2 g = upk(give);
            g.x = __shfl_xor_sync(0xffffffffu, g.x, off);
            g.y = __shfl_xor_sync(0xffffffffu, g.y, off);
            float2 kf = upk(keep);
            acc[v] = pk2(kf.x + g.x, kf.y + g.y);
        }
    }

    const int oo = lane >> 3, bp = lane & 7;
    const int o = ob + oo;
    const float bz = bias[o * LOCS + loc];
    float2 yv = upk(acc[0]);
    const float y0 = yv.x + bz;
    const float y1 = yv.y + bz;

    // per-channel partial stats (deterministic shfl tree over the 8 bp lanes)
    float s  = y0 + y1;
    float q2 = y0 * y0 + y1 * y1;
#pragma unroll
    for (int off = 4; off >= 1; off >>= 1) {
        s  += __shfl_xor_sync(0xffffffffu, s, off);
        q2 += __shfl_xor_sync(0xffffffffu, q2, off);
    }
    if (bp == 0) {
        g_psum[loc * COUT + o]   = s;
        g_psumsq[loc * COUT + o] = q2;
    }

    // stage outputs in smem (reuse patch buffer), one coalesced 4KB store
    __syncthreads();
    float* buf = ps;
    buf[(bp * 2) * COUT + o]     = y0;
    buf[(bp * 2 + 1) * COUT + o] = y1;
    __syncthreads();
    if (tid < 256) {
        float4* dst = (float4*)&g_y[loc * 1024];
        const float4* src = (const float4*)buf;
        dst[tid] = src[tid];
    }
}

// ---------------- kernel 2: finalize batch statistics ----------------
__global__ __launch_bounds__(256)
void stats_kernel(const float* __restrict__ gamma, const float* __restrict__ beta) {
    __shared__ float ss[256], sq[256];
    const int o = blockIdx.x, t = threadIdx.x;
    float s = 0.0f, q = 0.0f;
    for (int l = t; l < LOCS; l += 256) {
        s += g_psum[l * COUT + o];
        q += g_psumsq[l * COUT + o];
    }
    ss[t] = s; sq[t] = q;
    __syncthreads();
#pragma unroll
    for (int h = 128; h >= 1; h >>= 1) {
        if (t < h) { ss[t] += ss[t + h]; sq[t] += sq[t + h]; }
        __syncthreads();
    }
    if (t == 0) {
        const float N = (float)(BATCH * LOCS);
        float mean = ss[0] / N;
        float var  = sq[0] / N - mean * mean;
        float sc   = gamma[o] * rsqrtf(var + 1e-5f);
        g_scale[o] = sc;
        g_shift[o] = beta[o] - mean * sc;
    }
}

// ---------------- kernel 3: tiled transpose + BN affine + ReLU ----------------
__global__ __launch_bounds__(256)
void bn_kernel(float* __restrict__ out) {
    __shared__ float tile[32][33];
    __shared__ float s_sc[32], s_sh[32];
    const int t = threadIdx.x;
    const int tx = blockIdx.x;   // bo tile
    const int ty = blockIdx.y;   // loc tile
    if (t < 32) {
        int o = (tx * 32 + t) & 63;
        s_sc[t] = g_scale[o];
        s_sh[t] = g_shift[o];
    }
    const int lr = t >> 5;
    const int lc = t & 31;
#pragma unroll
    for (int p = 0; p < 4; p++) {
        int r = p * 8 + lr;
        tile[r][lc] = g_y[(ty * 32 + r) * 1024 + tx * 32 + lc];
    }
    __syncthreads();
#pragma unroll
    for (int p = 0; p < 4; p++) {
        int r = p * 8 + lr;
        int bo  = tx * 32 + r;
        int loc = ty * 32 + lc;
        float v = tile[lc][r] * s_sc[r] + s_sh[r];
        out[bo * 1024 + loc] = fmaxf(v, 0.0f);
    }
}

// ---------------- launch ----------------
extern "C" void kernel_launch(void* const* d_in, const int* in_sizes, int n_in,
                              void* d_out, int out_size) {
    const float* x     = (const float*)d_in[0];
    const float* w     = (const float*)d_in[1];
    const float* bias  = (const float*)d_in[2];
    const float* gamma = (const float*)d_in[3];
    const float* beta  = (const float*)d_in[4];
    float* out = (float*)d_out;

    conv_kernel<<<LOCS, 512>>>(x, w, bias);
    stats_kernel<<<COUT, 256>>>(gamma, beta);
    bn_kernel<<<dim3(32, 32), 256>>>(out);
}